// round 8
// baseline (speedup 1.0000x reference)
#include <cuda_runtime.h>
#include <cuda_bf16.h>
#include <cstdint>

#define BB 64
#define TT 512
#define DD 512
#define UU 512
#define NG 2048       // 4*UU
#define MM (BB * TT)  // 32768

// ---------------- device scratch (static: no allocations allowed) ----------------
__device__ float g_zx[(size_t)MM * NG];              // 268 MB: x @ Wk
__device__ __nv_bfloat16 g_xhi[(size_t)MM * DD];     // 32 MB
__device__ __nv_bfloat16 g_xlo[(size_t)MM * DD];     // 32 MB
__device__ __nv_bfloat16 g_wthi[(size_t)NG * DD];    // 2 MB (Wk^T [N][K])
__device__ __nv_bfloat16 g_wtlo[(size_t)NG * DD];    // 2 MB
__device__ __nv_bfloat16 g_wrhi[(size_t)NG * DD];    // 2 MB (Wr^T [N][K])
__device__ __nv_bfloat16 g_wrlo[(size_t)NG * DD];    // 2 MB
// zpart transposed, 4-slot ring: [slot][ks][col][b]  (16 MB)
__device__ float g_zpT[(size_t)4 * 8 * NG * BB];
// hidden state, 4-slot ring: [slot][b*512+u]
__device__ __nv_bfloat16 g_hhi4[4][BB * UU];
__device__ __nv_bfloat16 g_hlo4[4][BB * UU];
// counters: c1[q] at [q*32], q=0..3 (zpart ready);  c2[ks] at [(4+ks)*32] (h ready)
__device__ unsigned g_cnt[512];

// ---------------- helpers (arch-agnostic PTX only: compiles via compute_103) -----
__device__ __forceinline__ uint32_t smem_u32(const void* p) {
    uint32_t a;
    asm("{ .reg .u64 t; cvta.to.shared.u64 t, %1; cvt.u32.u64 %0, t; }" : "=r"(a) : "l"(p));
    return a;
}
#define SWZ128(b) ((b) ^ (((b) >> 3) & 0x70))

__device__ __forceinline__ void cp16(uint32_t saddr, const void* gptr) {
    asm volatile("cp.async.cg.shared.global [%0], [%1], 16;" :: "r"(saddr), "l"(gptr) : "memory");
}
#define CP_COMMIT() asm volatile("cp.async.commit_group;" ::: "memory")
#define CP_WAIT1()  asm volatile("cp.async.wait_group 1;" ::: "memory")

__device__ __forceinline__ void ldsm_x4(uint32_t* r, uint32_t addr) {
    asm volatile("ldmatrix.sync.aligned.m8n8.x4.shared.b16 {%0,%1,%2,%3}, [%4];"
                 : "=r"(r[0]), "=r"(r[1]), "=r"(r[2]), "=r"(r[3]) : "r"(addr));
}
__device__ __forceinline__ void ldsm_x2(uint32_t* r, uint32_t addr) {
    asm volatile("ldmatrix.sync.aligned.m8n8.x2.shared.b16 {%0,%1}, [%2];"
                 : "=r"(r[0]), "=r"(r[1]) : "r"(addr));
}
__device__ __forceinline__ void mma_bf16(float* c, const uint32_t* a, const uint32_t* b) {
    asm volatile(
        "mma.sync.aligned.m16n8k16.row.col.f32.bf16.bf16.f32 "
        "{%0,%1,%2,%3}, {%4,%5,%6,%7}, {%8,%9}, {%0,%1,%2,%3};"
        : "+f"(c[0]), "+f"(c[1]), "+f"(c[2]), "+f"(c[3])
        : "r"(a[0]), "r"(a[1]), "r"(a[2]), "r"(a[3]), "r"(b[0]), "r"(b[1]));
}

// ---------------- fine-grained sync: release RED bump / acquire poll --------------
__device__ __forceinline__ void bump_cnt(unsigned* c) {
    __syncthreads();   // all CTA threads' prior global writes ordered before release
    if (threadIdx.x == 0)
        asm volatile("red.release.gpu.global.add.u32 [%0], %1;" :: "l"(c), "r"(1u) : "memory");
}
__device__ __forceinline__ void wait_cnt(unsigned* c, unsigned tgt) {
    if (threadIdx.x == 0) {
        unsigned v;
        do {
            asm volatile("ld.acquire.gpu.global.u32 %0, [%1];" : "=r"(v) : "l"(c) : "memory");
            if (v < tgt) __nanosleep(16);
        } while (v < tgt);
    }
    __syncthreads();   // publish acquire to all CTA threads
}

// ---------------- fast transcendentals (MUFU-based, ~1e-6 rel err) ----------------
__device__ __forceinline__ float fsigmoid(float x) { return 1.0f / (1.0f + __expf(-x)); }
__device__ __forceinline__ float ftanh(float x) { return 2.0f / (1.0f + __expf(-2.0f * x)) - 1.0f; }

// =======================================================================
// Prep 1: x fp32 -> bf16 hi/lo split.
// =======================================================================
__global__ __launch_bounds__(256) void prep_x(const float* __restrict__ x) {
    size_t i = (size_t)blockIdx.x * 256 + threadIdx.x;
    const size_t n4 = (size_t)MM * DD / 4;
    if (i >= n4) return;
    float4 v = ((const float4*)x)[i];
    __nv_bfloat16 h0 = __float2bfloat16(v.x), h1 = __float2bfloat16(v.y);
    __nv_bfloat16 h2 = __float2bfloat16(v.z), h3 = __float2bfloat16(v.w);
    __nv_bfloat16 l0 = __float2bfloat16(v.x - __bfloat162float(h0));
    __nv_bfloat16 l1 = __float2bfloat16(v.y - __bfloat162float(h1));
    __nv_bfloat16 l2 = __float2bfloat16(v.z - __bfloat162float(h2));
    __nv_bfloat16 l3 = __float2bfloat16(v.w - __bfloat162float(h3));
    ((__nv_bfloat162*)g_xhi)[2 * i]     = __nv_bfloat162(h0, h1);
    ((__nv_bfloat162*)g_xhi)[2 * i + 1] = __nv_bfloat162(h2, h3);
    ((__nv_bfloat162*)g_xlo)[2 * i]     = __nv_bfloat162(l0, l1);
    ((__nv_bfloat162*)g_xlo)[2 * i + 1] = __nv_bfloat162(l2, l3);
}

// =======================================================================
// Prep 2: W [K=512][N=2048] fp32 -> transposed bf16 hi/lo [N][K].
// =======================================================================
__global__ __launch_bounds__(256) void prep_wt(const float* __restrict__ W,
                                               __nv_bfloat16* __restrict__ dhi,
                                               __nv_bfloat16* __restrict__ dlo) {
    __shared__ float s[32][33];
    const int n0 = blockIdx.x * 32;
    const int k0 = blockIdx.y * 32;
    const int tx = threadIdx.x & 31;
    const int ty = threadIdx.x >> 5;
#pragma unroll
    for (int j = 0; j < 32; j += 8)
        s[ty + j][tx] = W[(size_t)(k0 + ty + j) * NG + n0 + tx];
    __syncthreads();
#pragma unroll
    for (int j = 0; j < 32; j += 8) {
        float v = s[tx][ty + j];
        __nv_bfloat16 h = __float2bfloat16(v);
        __nv_bfloat16 l = __float2bfloat16(v - __bfloat162float(h));
        size_t o = (size_t)(n0 + ty + j) * DD + k0 + tx;
        dhi[o] = h;
        dlo[o] = l;
    }
}

// =======================================================================
// Phase 1 GEMM (mma.sync bf16 x3): zx = x @ Wk   (validated R3/R5/R7)
// =======================================================================
#define STAGE_BYTES 65536
#define SA_HI 0
#define SA_LO 16384
#define SB_HI 32768
#define SB_LO 49152
#define GEMM_SMEM (2 * STAGE_BYTES)

__device__ __forceinline__ void load_stage(uint32_t sbase, int m0, int n0, int kc, int tid) {
    const uint32_t ksrc = (uint32_t)kc * 128;
    const char* pxh = (const char*)g_xhi;
    const char* pxl = (const char*)g_xlo;
    const char* pwh = (const char*)g_wthi;
    const char* pwl = (const char*)g_wtlo;
#pragma unroll
    for (int i = 0; i < 4; i++) {
        int idx = i * 256 + tid;
        int row = idx >> 3;
        uint32_t q = (uint32_t)(idx & 7) * 16;
        uint32_t sw = SWZ128((uint32_t)row * 128 + q);
        size_t asrc = (size_t)(m0 + row) * 1024 + ksrc + q;
        size_t bsrc = (size_t)(n0 + row) * 1024 + ksrc + q;
        cp16(sbase + SA_HI + sw, pxh + asrc);
        cp16(sbase + SA_LO + sw, pxl + asrc);
        cp16(sbase + SB_HI + sw, pwh + bsrc);
        cp16(sbase + SB_LO + sw, pwl + bsrc);
    }
}

__global__ __launch_bounds__(256) void gemm_zx_mma() {
    extern __shared__ __align__(1024) char smem[];
    const uint32_t sb = smem_u32(smem);
    const int tid = threadIdx.x;
    const int wid = tid >> 5, lid = tid & 31;
    const int n0 = blockIdx.x * 128, m0 = blockIdx.y * 128;
    const int wm = wid & 1;
    const int wn = wid >> 1;

    float acc[4][4][4];
#pragma unroll
    for (int mf = 0; mf < 4; mf++)
#pragma unroll
        for (int nf = 0; nf < 4; nf++)
#pragma unroll
            for (int e = 0; e < 4; e++) acc[mf][nf][e] = 0.0f;

    load_stage(sb, m0, n0, 0, tid);
    CP_COMMIT();

    for (int kc = 0; kc < 8; kc++) {
        if (kc < 7) load_stage(sb + ((kc + 1) & 1) * STAGE_BYTES, m0, n0, kc + 1, tid);
        CP_COMMIT();
        CP_WAIT1();
        __syncthreads();

        const uint32_t st = sb + (kc & 1) * STAGE_BYTES;
        const int la = lid & 15;
        const uint32_t a_koff = (uint32_t)(lid >> 4) * 16;
        const uint32_t b_koff = (uint32_t)((la >> 3) & 1) * 16;

#pragma unroll
        for (int k16 = 0; k16 < 4; k16++) {
            const uint32_t kb = (uint32_t)k16 * 32;
            uint32_t ah[4][4], al[4][4];
#pragma unroll
            for (int mf = 0; mf < 4; mf++) {
                uint32_t row = (uint32_t)(wm * 64 + mf * 16 + la);
                uint32_t sw = SWZ128(row * 128 + kb + a_koff);
                ldsm_x4(ah[mf], st + SA_HI + sw);
                ldsm_x4(al[mf], st + SA_LO + sw);
            }
            uint32_t bh[4][2], bl[4][2];
#pragma unroll
            for (int nf = 0; nf < 4; nf++) {
                uint32_t nrow = (uint32_t)(wn * 32 + nf * 8 + (la & 7));
                uint32_t sw = SWZ128(nrow * 128 + kb + b_koff);
                ldsm_x2(bh[nf], st + SB_HI + sw);
                ldsm_x2(bl[nf], st + SB_LO + sw);
            }
#pragma unroll
            for (int mf = 0; mf < 4; mf++)
#pragma unroll
                for (int nf = 0; nf < 4; nf++) {
                    mma_bf16(acc[mf][nf], ah[mf], bh[nf]);
                    mma_bf16(acc[mf][nf], ah[mf], bl[nf]);
                    mma_bf16(acc[mf][nf], al[mf], bh[nf]);
                }
        }
        __syncthreads();
    }

    const int g = lid >> 2, tig = lid & 3;
#pragma unroll
    for (int mf = 0; mf < 4; mf++) {
        int row = m0 + wm * 64 + mf * 16 + g;
        float* b0 = g_zx + (size_t)row * NG + n0 + wn * 32;
        float* b1 = b0 + (size_t)8 * NG;
#pragma unroll
        for (int nf = 0; nf < 4; nf++) {
            *(float2*)(b0 + nf * 8 + 2 * tig) = make_float2(acc[mf][nf][0], acc[mf][nf][1]);
            *(float2*)(b1 + nf * 8 + 2 * tig) = make_float2(acc[mf][nf][2], acc[mf][nf][3]);
        }
    }
}

// =======================================================================
// Phase 2: persistent LSTM recurrence — dataflow sync (NO global barrier).
// 128 CTAs x 256 thr. Producer role (cg=blk>>3, ks=blk&7): HMMA partial
// GEMM, zpart written transposed to a 4-slot ring; bump c1[cg&3].
// Gate role (block blk owns units [blk*4,+4) x 64 batches, tid=b*4+du):
// wait c1[blk>>5], reduce 8 partials + gates, write h to 4-slot ring,
// bump c2[blk>>4]. Stager waits c2[ks] for its h slice.
// =======================================================================
#define R_WHI 0
#define R_WLO 16384
#define R_HHI 32768
#define R_HLO 40960
#define REC_SMEM 49152

__global__ __launch_bounds__(256) void lstm_recur(const float* __restrict__ bias,
                                                  float* __restrict__ out) {
    extern __shared__ __align__(1024) char rsm[];
    const uint32_t sb = smem_u32(rsm);
    const int tid = threadIdx.x;
    const int wid = tid >> 5, lid = tid & 31;
    const int blk = blockIdx.x;
    const int cg = blk >> 3;   // 0..15 column group (128 cols)
    const int ks = blk & 7;    // 0..7  K slice (64 rows) -- ALSO its h-slice need
    const int wn = wid;        // 8 warps along N: 16 cols each

    unsigned* c1_prod = &g_cnt[(cg & 3) * 32];        // I produce zpart for group cg%4
    unsigned* c1_cons = &g_cnt[(blk >> 5) * 32];      // my gate units live in group blk/32
    unsigned* c2_prod = &g_cnt[(4 + (blk >> 4)) * 32];// my gate units are in h-slice blk/16
    unsigned* c2_cons = &g_cnt[(4 + ks) * 32];        // I stage h-slice ks

    // ---- load persistent Wr^T slice into smem (SW128) ----
#pragma unroll
    for (int r = 0; r < 4; r++) {
        int i = r * 256 + tid;
        int row = i >> 3;
        uint32_t q = (uint32_t)(i & 7) * 16;
        uint32_t sw = SWZ128((uint32_t)row * 128 + q);
        size_t src = (size_t)(cg * 128 + row) * 1024 + (size_t)ks * 128 + q;
        *(float4*)(rsm + R_WHI + sw) = *(const float4*)((const char*)g_wrhi + src);
        *(float4*)(rsm + R_WLO + sw) = *(const float4*)((const char*)g_wrlo + src);
    }

    // ---- gate-role thread mapping: tid = b*4 + du ----
    const int bb = tid >> 2;          // 0..63
    const int du = tid & 3;           // 0..3
    const int ub = blk * 4 + du;      // unit 0..511
    const int hoff = bb * UU + ub;    // index into h slot

    // zero h(-1) = slot 3, then announce (also orders Wr smem via bump's syncthreads)
    g_hhi4[3][hoff] = __float2bfloat16(0.0f);
    g_hlo4[3][hoff] = __float2bfloat16(0.0f);
    float c_reg = 0.0f;
    bump_cnt(c2_prod);                // c2[slice] reaches 16 == "h(-1) ready"

    // ---- preload B fragments (Wr) into registers (after bump's syncthreads) ----
    const int la = lid & 15;
    const uint32_t a_koff = (uint32_t)(lid >> 4) * 16;
    const uint32_t b_koff = (uint32_t)((la >> 3) & 1) * 16;
    uint32_t bhfr[2][4][2], blfr[2][4][2];
#pragma unroll
    for (int nf = 0; nf < 2; nf++)
#pragma unroll
        for (int k16 = 0; k16 < 4; k16++) {
            uint32_t nrow = (uint32_t)(wn * 16 + nf * 8 + (la & 7));
            uint32_t sw = SWZ128(nrow * 128 + (uint32_t)k16 * 32 + b_koff);
            ldsm_x2(bhfr[nf][k16], sb + R_WHI + sw);
            ldsm_x2(blfr[nf][k16], sb + R_WLO + sw);
        }

    const int g = lid >> 2, tig = lid & 3;

    for (int t = 0; t < TT; t++) {
        // ---- prefetch zx(t) for gate role (independent of all sync) ----
        const float* zxp = &g_zx[((size_t)bb * TT + t) * NG + ub];
        float zx0 = __ldg(zxp);
        float zx1 = __ldg(zxp + 512);
        float zx2 = __ldg(zxp + 1024);
        float zx3 = __ldg(zxp + 1536);

        // ---- wait h(t-1) slice ks ready, stage into smem ----
        wait_cnt(c2_cons, 16u * (unsigned)(t + 1));
        {
            const char* hh = (const char*)g_hhi4[(t + 3) & 3];
            const char* hl = (const char*)g_hlo4[(t + 3) & 3];
#pragma unroll
            for (int r = 0; r < 2; r++) {
                int i = r * 256 + tid;
                int row = i >> 3;                 // batch 0..63
                uint32_t q = (uint32_t)(i & 7) * 16;
                uint32_t sw = SWZ128((uint32_t)row * 128 + q);
                size_t src = (size_t)row * 1024 + (size_t)ks * 128 + q;
                *(float4*)(rsm + R_HHI + sw) = __ldcg((const float4*)(hh + src));
                *(float4*)(rsm + R_HLO + sw) = __ldcg((const float4*)(hl + src));
            }
        }
        __syncthreads();

        float acc[4][2][4];
#pragma unroll
        for (int mf = 0; mf < 4; mf++)
#pragma unroll
            for (int nf = 0; nf < 2; nf++)
#pragma unroll
                for (int e = 0; e < 4; e++) acc[mf][nf][e] = 0.0f;

#pragma unroll
        for (int k16 = 0; k16 < 4; k16++) {
            const uint32_t kb = (uint32_t)k16 * 32;
            uint32_t ah[4][4], al[4][4];
#pragma unroll
            for (int mf = 0; mf < 4; mf++) {
                uint32_t row = (uint32_t)(mf * 16 + la);
                uint32_t sw = SWZ128(row * 128 + kb + a_koff);
                ldsm_x4(ah[mf], sb + R_HHI + sw);
                ldsm_x4(al[mf], sb + R_HLO + sw);
            }
#pragma unroll
            for (int mf = 0; mf < 4; mf++)
#pragma unroll
                for (int nf = 0; nf < 2; nf++) {
                    mma_bf16(acc[mf][nf], ah[mf], bhfr[nf][k16]);
                    mma_bf16(acc[mf][nf], ah[mf], blfr[nf][k16]);
                    mma_bf16(acc[mf][nf], al[mf], bhfr[nf][k16]);
                }
        }

        // ---- write zpart(t) TRANSPOSED [col][b] into slot t&3, announce ----
        {
            float* zb = g_zpT + (((size_t)(t & 3) * 8 + ks) * NG) * BB;
#pragma unroll
            for (int mf = 0; mf < 4; mf++) {
                int b0 = mf * 16 + g;
#pragma unroll
                for (int nf = 0; nf < 2; nf++) {
                    int c0 = cg * 128 + wn * 16 + nf * 8 + 2 * tig;
                    zb[(size_t)c0 * BB + b0]           = acc[mf][nf][0];
                    zb[(size_t)(c0 + 1) * BB + b0]     = acc[mf][nf][1];
                    zb[(size_t)c0 * BB + b0 + 8]       = acc[mf][nf][2];
                    zb[(size_t)(c0 + 1) * BB + b0 + 8] = acc[mf][nf][3];
                }
            }
        }
        bump_cnt(c1_prod);

        // ---- wait zpart(t) for my unit group, reduce + gates ----
        wait_cnt(c1_cons, 32u * (unsigned)(t + 1));
        {
            float z0 = bias[ub]        + zx0;
            float z1 = bias[512 + ub]  + zx1;
            float z2 = bias[1024 + ub] + zx2;
            float z3 = bias[1536 + ub] + zx3;
            const float* zslot = g_zpT + ((size_t)(t & 3) * 8) * NG * BB;
#pragma unroll
            for (int s = 0; s < 8; s++) {
                const float* zp = zslot + (size_t)s * NG * BB + bb;
                z0 += __ldcg(zp + (size_t)ub * BB);
                z1 += __ldcg(zp + (size_t)(512 + ub) * BB);
                z2 += __ldcg(zp + (size_t)(1024 + ub) * BB);
                z3 += __ldcg(zp + (size_t)(1536 + ub) * BB);
            }
            float ig = fsigmoid(z0);
            float fg = fsigmoid(z1);
            float gg = ftanh(z2);
            float og = fsigmoid(z3);
            float cv = fg * c_reg + ig * gg;
            c_reg = cv;
            float hv = og * ftanh(cv);
            __nv_bfloat16 hh = __float2bfloat16(hv);
            g_hhi4[t & 3][hoff] = hh;
            g_hlo4[t & 3][hoff] = __float2bfloat16(hv - __bfloat162float(hh));
            if (t == TT - 1) out[hoff] = hv;
        }
        bump_cnt(c2_prod);
    }
}

// =======================================================================
extern "C" void kernel_launch(void* const* d_in, const int* in_sizes, int n_in,
                              void* d_out, int out_size) {
    const float* x  = (const float*)d_in[0];
    const float* Wk = (const float*)d_in[1];
    const float* Wr = (const float*)d_in[2];
    const float* b  = (const float*)d_in[3];
    float* out = (float*)d_out;

    cudaFuncSetAttribute(gemm_zx_mma, cudaFuncAttributeMaxDynamicSharedMemorySize, GEMM_SMEM);
    cudaFuncSetAttribute(lstm_recur, cudaFuncAttributeMaxDynamicSharedMemorySize, REC_SMEM);

    // Resolve DEVICE addresses of __device__ symbols on the host.
    void *cnt_ptr, *wthi, *wtlo, *wrhi, *wrlo;
    cudaGetSymbolAddress(&cnt_ptr, g_cnt);
    cudaGetSymbolAddress(&wthi, g_wthi);
    cudaGetSymbolAddress(&wtlo, g_wtlo);
    cudaGetSymbolAddress(&wrhi, g_wrhi);
    cudaGetSymbolAddress(&wrlo, g_wrlo);

    cudaMemsetAsync(cnt_ptr, 0, 512 * sizeof(unsigned));   // graph-capturable

    prep_x<<<(MM * DD / 4 + 255) / 256, 256>>>(x);
    prep_wt<<<dim3(NG / 32, DD / 32), 256>>>(Wk, (__nv_bfloat16*)wthi, (__nv_bfloat16*)wtlo);
    prep_wt<<<dim3(NG / 32, DD / 32), 256>>>(Wr, (__nv_bfloat16*)wrhi, (__nv_bfloat16*)wrlo);
    gemm_zx_mma<<<dim3(NG / 128, MM / 128), 256, GEMM_SMEM>>>();
    lstm_recur<<<128, 256, REC_SMEM>>>(b, out);
}

// round 9
// speedup vs baseline: 1.2105x; 1.2105x over previous
#include <cuda_runtime.h>
#include <cuda_bf16.h>
#include <cstdint>

#define BB 64
#define TT 512
#define DD 512
#define UU 512
#define NG 2048       // 4*UU
#define MM (BB * TT)  // 32768

// ---------------- device scratch (static: no allocations allowed) ----------------
__device__ float g_zx[(size_t)MM * NG];              // 268 MB: x @ Wk
__device__ __nv_bfloat16 g_xhi[(size_t)MM * DD];     // 32 MB
__device__ __nv_bfloat16 g_xlo[(size_t)MM * DD];     // 32 MB
__device__ __nv_bfloat16 g_wthi[(size_t)NG * DD];    // 2 MB (Wk^T [N][K])
__device__ __nv_bfloat16 g_wtlo[(size_t)NG * DD];    // 2 MB
__device__ __nv_bfloat16 g_wrhi[(size_t)NG * DD];    // 2 MB (Wr^T, GATE-INTERLEAVED rows)
__device__ __nv_bfloat16 g_wrlo[(size_t)NG * DD];    // 2 MB
// hidden state 4-slot ring: [slot][bg][b_l*512 + u]  (16 batches per bg)
__device__ __nv_bfloat16 g_hhi4[4 * 4 * 16 * UU];
__device__ __nv_bfloat16 g_hlo4[4 * 4 * 16 * UU];
__device__ unsigned g_cnt[512];                      // counter per bg at [bg*32]

// ---------------- helpers (arch-agnostic PTX only: compiles via compute_103) -----
__device__ __forceinline__ uint32_t smem_u32(const void* p) {
    uint32_t a;
    asm("{ .reg .u64 t; cvta.to.shared.u64 t, %1; cvt.u32.u64 %0, t; }" : "=r"(a) : "l"(p));
    return a;
}
#define SWZ128(b) ((b) ^ (((b) >> 3) & 0x70))

__device__ __forceinline__ void cp16(uint32_t saddr, const void* gptr) {
    asm volatile("cp.async.cg.shared.global [%0], [%1], 16;" :: "r"(saddr), "l"(gptr) : "memory");
}
#define CP_COMMIT() asm volatile("cp.async.commit_group;" ::: "memory")
#define CP_WAIT1()  asm volatile("cp.async.wait_group 1;" ::: "memory")

__device__ __forceinline__ void ldsm_x4(uint32_t* r, uint32_t addr) {
    asm volatile("ldmatrix.sync.aligned.m8n8.x4.shared.b16 {%0,%1,%2,%3}, [%4];"
                 : "=r"(r[0]), "=r"(r[1]), "=r"(r[2]), "=r"(r[3]) : "r"(addr));
}
__device__ __forceinline__ void ldsm_x2(uint32_t* r, uint32_t addr) {
    asm volatile("ldmatrix.sync.aligned.m8n8.x2.shared.b16 {%0,%1}, [%2];"
                 : "=r"(r[0]), "=r"(r[1]) : "r"(addr));
}
__device__ __forceinline__ void mma_bf16(float* c, const uint32_t* a, const uint32_t* b) {
    asm volatile(
        "mma.sync.aligned.m16n8k16.row.col.f32.bf16.bf16.f32 "
        "{%0,%1,%2,%3}, {%4,%5,%6,%7}, {%8,%9}, {%0,%1,%2,%3};"
        : "+f"(c[0]), "+f"(c[1]), "+f"(c[2]), "+f"(c[3])
        : "r"(a[0]), "r"(a[1]), "r"(a[2]), "r"(a[3]), "r"(b[0]), "r"(b[1]));
}

// ---------------- sync: release RED bump / acquire poll ---------------------------
__device__ __forceinline__ void bump_cnt(unsigned* c) {
    __syncthreads();
    if (threadIdx.x == 0)
        asm volatile("red.release.gpu.global.add.u32 [%0], %1;" :: "l"(c), "r"(1u) : "memory");
}
__device__ __forceinline__ void wait_cnt(unsigned* c, unsigned tgt) {
    if (threadIdx.x == 0) {
        unsigned v;
        do {
            asm volatile("ld.acquire.gpu.global.u32 %0, [%1];" : "=r"(v) : "l"(c) : "memory");
            if (v < tgt) __nanosleep(16);
        } while (v < tgt);
    }
    __syncthreads();
}

// ---------------- fast transcendentals ----------------
__device__ __forceinline__ float fsigmoid(float x) { return 1.0f / (1.0f + __expf(-x)); }
__device__ __forceinline__ float ftanh(float x) { return 2.0f / (1.0f + __expf(-2.0f * x)) - 1.0f; }

// =======================================================================
// Prep 1: x fp32 -> bf16 hi/lo split.
// =======================================================================
__global__ __launch_bounds__(256) void prep_x(const float* __restrict__ x) {
    size_t i = (size_t)blockIdx.x * 256 + threadIdx.x;
    const size_t n4 = (size_t)MM * DD / 4;
    if (i >= n4) return;
    float4 v = ((const float4*)x)[i];
    __nv_bfloat16 h0 = __float2bfloat16(v.x), h1 = __float2bfloat16(v.y);
    __nv_bfloat16 h2 = __float2bfloat16(v.z), h3 = __float2bfloat16(v.w);
    __nv_bfloat16 l0 = __float2bfloat16(v.x - __bfloat162float(h0));
    __nv_bfloat16 l1 = __float2bfloat16(v.y - __bfloat162float(h1));
    __nv_bfloat16 l2 = __float2bfloat16(v.z - __bfloat162float(h2));
    __nv_bfloat16 l3 = __float2bfloat16(v.w - __bfloat162float(h3));
    ((__nv_bfloat162*)g_xhi)[2 * i]     = __nv_bfloat162(h0, h1);
    ((__nv_bfloat162*)g_xhi)[2 * i + 1] = __nv_bfloat162(h2, h3);
    ((__nv_bfloat162*)g_xlo)[2 * i]     = __nv_bfloat162(l0, l1);
    ((__nv_bfloat162*)g_xlo)[2 * i + 1] = __nv_bfloat162(l2, l3);
}

// =======================================================================
// Prep 2a: Wk -> transposed bf16 hi/lo [N][K] (original column order).
// =======================================================================
__global__ __launch_bounds__(256) void prep_wt(const float* __restrict__ W,
                                               __nv_bfloat16* __restrict__ dhi,
                                               __nv_bfloat16* __restrict__ dlo) {
    __shared__ float s[32][33];
    const int n0 = blockIdx.x * 32;
    const int k0 = blockIdx.y * 32;
    const int tx = threadIdx.x & 31;
    const int ty = threadIdx.x >> 5;
#pragma unroll
    for (int j = 0; j < 32; j += 8)
        s[ty + j][tx] = W[(size_t)(k0 + ty + j) * NG + n0 + tx];
    __syncthreads();
#pragma unroll
    for (int j = 0; j < 32; j += 8) {
        float v = s[tx][ty + j];
        __nv_bfloat16 h = __float2bfloat16(v);
        __nv_bfloat16 l = __float2bfloat16(v - __bfloat162float(h));
        size_t o = (size_t)(n0 + ty + j) * DD + k0 + tx;
        dhi[o] = h;
        dlo[o] = l;
    }
}

// =======================================================================
// Prep 2b: Wr -> transposed bf16 hi/lo, GATE-INTERLEAVED rows:
// output row n' = (n % 512)*4 + (n / 512)  (unit-major, gate-minor).
// =======================================================================
__global__ __launch_bounds__(256) void prep_wr(const float* __restrict__ W,
                                               __nv_bfloat16* __restrict__ dhi,
                                               __nv_bfloat16* __restrict__ dlo) {
    __shared__ float s[32][33];
    const int n0 = blockIdx.x * 32;
    const int k0 = blockIdx.y * 32;
    const int tx = threadIdx.x & 31;
    const int ty = threadIdx.x >> 5;
#pragma unroll
    for (int j = 0; j < 32; j += 8)
        s[ty + j][tx] = W[(size_t)(k0 + ty + j) * NG + n0 + tx];
    __syncthreads();
#pragma unroll
    for (int j = 0; j < 32; j += 8) {
        float v = s[tx][ty + j];
        __nv_bfloat16 h = __float2bfloat16(v);
        __nv_bfloat16 l = __float2bfloat16(v - __bfloat162float(h));
        int n = n0 + ty + j;
        int nperm = (n & 511) * 4 + (n >> 9);
        size_t o = (size_t)nperm * DD + k0 + tx;
        dhi[o] = h;
        dlo[o] = l;
    }
}

// =======================================================================
// Phase 1 GEMM (mma.sync bf16 x3): zx = x @ Wk   (validated R3/R5/R7)
// =======================================================================
#define STAGE_BYTES 65536
#define SA_HI 0
#define SA_LO 16384
#define SB_HI 32768
#define SB_LO 49152
#define GEMM_SMEM (2 * STAGE_BYTES)

__device__ __forceinline__ void load_stage(uint32_t sbase, int m0, int n0, int kc, int tid) {
    const uint32_t ksrc = (uint32_t)kc * 128;
    const char* pxh = (const char*)g_xhi;
    const char* pxl = (const char*)g_xlo;
    const char* pwh = (const char*)g_wthi;
    const char* pwl = (const char*)g_wtlo;
#pragma unroll
    for (int i = 0; i < 4; i++) {
        int idx = i * 256 + tid;
        int row = idx >> 3;
        uint32_t q = (uint32_t)(idx & 7) * 16;
        uint32_t sw = SWZ128((uint32_t)row * 128 + q);
        size_t asrc = (size_t)(m0 + row) * 1024 + ksrc + q;
        size_t bsrc = (size_t)(n0 + row) * 1024 + ksrc + q;
        cp16(sbase + SA_HI + sw, pxh + asrc);
        cp16(sbase + SA_LO + sw, pxl + asrc);
        cp16(sbase + SB_HI + sw, pwh + bsrc);
        cp16(sbase + SB_LO + sw, pwl + bsrc);
    }
}

__global__ __launch_bounds__(256) void gemm_zx_mma() {
    extern __shared__ __align__(1024) char smem[];
    const uint32_t sb = smem_u32(smem);
    const int tid = threadIdx.x;
    const int wid = tid >> 5, lid = tid & 31;
    const int n0 = blockIdx.x * 128, m0 = blockIdx.y * 128;
    const int wm = wid & 1;
    const int wn = wid >> 1;

    float acc[4][4][4];
#pragma unroll
    for (int mf = 0; mf < 4; mf++)
#pragma unroll
        for (int nf = 0; nf < 4; nf++)
#pragma unroll
            for (int e = 0; e < 4; e++) acc[mf][nf][e] = 0.0f;

    load_stage(sb, m0, n0, 0, tid);
    CP_COMMIT();

    for (int kc = 0; kc < 8; kc++) {
        if (kc < 7) load_stage(sb + ((kc + 1) & 1) * STAGE_BYTES, m0, n0, kc + 1, tid);
        CP_COMMIT();
        CP_WAIT1();
        __syncthreads();

        const uint32_t st = sb + (kc & 1) * STAGE_BYTES;
        const int la = lid & 15;
        const uint32_t a_koff = (uint32_t)(lid >> 4) * 16;
        const uint32_t b_koff = (uint32_t)((la >> 3) & 1) * 16;

#pragma unroll
        for (int k16 = 0; k16 < 4; k16++) {
            const uint32_t kb = (uint32_t)k16 * 32;
            uint32_t ah[4][4], al[4][4];
#pragma unroll
            for (int mf = 0; mf < 4; mf++) {
                uint32_t row = (uint32_t)(wm * 64 + mf * 16 + la);
                uint32_t sw = SWZ128(row * 128 + kb + a_koff);
                ldsm_x4(ah[mf], st + SA_HI + sw);
                ldsm_x4(al[mf], st + SA_LO + sw);
            }
            uint32_t bh[4][2], bl[4][2];
#pragma unroll
            for (int nf = 0; nf < 4; nf++) {
                uint32_t nrow = (uint32_t)(wn * 32 + nf * 8 + (la & 7));
                uint32_t sw = SWZ128(nrow * 128 + kb + b_koff);
                ldsm_x2(bh[nf], st + SB_HI + sw);
                ldsm_x2(bl[nf], st + SB_LO + sw);
            }
#pragma unroll
            for (int mf = 0; mf < 4; mf++)
#pragma unroll
                for (int nf = 0; nf < 4; nf++) {
                    mma_bf16(acc[mf][nf], ah[mf], bh[nf]);
                    mma_bf16(acc[mf][nf], ah[mf], bl[nf]);
                    mma_bf16(acc[mf][nf], al[mf], bh[nf]);
                }
        }
        __syncthreads();
    }

    const int g = lid >> 2, tig = lid & 3;
#pragma unroll
    for (int mf = 0; mf < 4; mf++) {
        int row = m0 + wm * 64 + mf * 16 + g;
        float* b0 = g_zx + (size_t)row * NG + n0 + wn * 32;
        float* b1 = b0 + (size_t)8 * NG;
#pragma unroll
        for (int nf = 0; nf < 4; nf++) {
            *(float2*)(b0 + nf * 8 + 2 * tig) = make_float2(acc[mf][nf][0], acc[mf][nf][1]);
            *(float2*)(b1 + nf * 8 + 2 * tig) = make_float2(acc[mf][nf][2], acc[mf][nf][3]);
        }
    }
}

// =======================================================================
// Phase 2: persistent LSTM recurrence — UNIT-COMPLETE CTAs, one sync hop.
// 128 CTAs = 32 col-groups (16 units, gate-interleaved) x 4 batch-groups
// (16 batches). Full K=512 per CTA: Wr slice 128KB smem, gates+c local.
// Per step: wait group h(t-1) -> stage A -> mma (full z) -> smem exchange
// -> gates (c in register) -> publish h(t) -> bump group counter.
// =======================================================================
#define S_BHI 0
#define S_BLO 65536
#define S_AHI 131072
#define S_ALO 147456
#define S_Z   163840
#define REC2_SMEM (S_Z + 64 * 16 * 4)   // 167936

__global__ __launch_bounds__(256) void lstm_recur2(const float* __restrict__ bias,
                                                   float* __restrict__ out) {
    extern __shared__ __align__(1024) char rsm[];
    const uint32_t sb = smem_u32(rsm);
    const int tid = threadIdx.x;
    const int wid = tid >> 5, lid = tid & 31;
    const int blk = blockIdx.x;
    const int bg = blk & 3;     // batch group: batches [bg*16, +16)
    const int cg = blk >> 2;    // col group: units [cg*16, +16) = cols' [cg*64, +64)
    const int wn = wid;         // warp -> 8 cols' (2 units)
    unsigned* ctr = &g_cnt[bg * 32];

    // ---- fill persistent Wr' slice: [chunk(8)][col(64)] rows of 128B, hi/lo ----
    {
        const char* wh = (const char*)g_wrhi;
        const char* wl = (const char*)g_wrlo;
#pragma unroll
        for (int r = 0; r < 16; r++) {
            int i = r * 256 + tid;            // 0..4095
            int rowf = i >> 3;                // 0..511 = kc*64 + c
            uint32_t q = (uint32_t)(i & 7) * 16;
            int kc = rowf >> 6, c = rowf & 63;
            uint32_t sw = SWZ128((uint32_t)rowf * 128 + q);
            size_t src = (size_t)(cg * 64 + c) * 1024 + (size_t)kc * 128 + q;
            *(float4*)(rsm + S_BHI + sw) = *(const float4*)(wh + src);
            *(float4*)(rsm + S_BLO + sw) = *(const float4*)(wl + src);
        }
    }

    // ---- thread ownership for gates: tid = u_l*16 + b_l ----
    const int u_l = tid >> 4;           // 0..15
    const int b_l = tid & 15;           // 0..15
    const int u = cg * 16 + u_l;        // unit 0..511
    const int b_glob = bg * 16 + b_l;   // batch 0..63
    const int hoff = b_l * UU + u;      // within [slot][bg] block

    // h(-1) = 0 into slot 3; bump announces (and orders smem fill via its syncthreads)
    g_hhi4[(3 * 4 + bg) * (16 * UU) + hoff] = __float2bfloat16(0.0f);
    g_hlo4[(3 * 4 + bg) * (16 * UU) + hoff] = __float2bfloat16(0.0f);
    float c_reg = 0.0f;
    bump_cnt(ctr);                      // counter reaches 32 == h(-1) ready

    const int la = lid & 15;
    const uint32_t a_koff = (uint32_t)(lid >> 4) * 16;
    const uint32_t b_koff = (uint32_t)((la >> 3) & 1) * 16;
    const int g = lid >> 2, tig = lid & 3;
    float* z_s = (float*)(rsm + S_Z);   // [col_local(64)][b(16)]

    for (int t = 0; t < TT; t++) {
        // ---- prefetch zx(t) (original column order; independent of sync) ----
        const float* zxp = &g_zx[((size_t)b_glob * TT + t) * NG + u];
        float zx0 = __ldg(zxp);
        float zx1 = __ldg(zxp + 512);
        float zx2 = __ldg(zxp + 1024);
        float zx3 = __ldg(zxp + 1536);

        // ---- ONE sync hop: wait group h(t-1) ----
        wait_cnt(ctr, 32u * (unsigned)(t + 1));

        // ---- stage A = h(t-1) [16 batches x 512 units]: [chunk(8)][b(16)] rows ----
        {
            const char* hh = (const char*)g_hhi4 + (size_t)(((t + 3) & 3) * 4 + bg) * (16 * UU) * 2;
            const char* hl = (const char*)g_hlo4 + (size_t)(((t + 3) & 3) * 4 + bg) * (16 * UU) * 2;
#pragma unroll
            for (int r = 0; r < 4; r++) {
                int i = r * 256 + tid;          // 0..1023
                int rowf = i >> 3;              // 0..127 = kc*16 + b
                uint32_t q = (uint32_t)(i & 7) * 16;
                int kc = rowf >> 4, bb2 = rowf & 15;
                uint32_t sw = SWZ128((uint32_t)rowf * 128 + q);
                size_t src = (size_t)bb2 * 1024 + (size_t)kc * 128 + q;
                *(float4*)(rsm + S_AHI + sw) = __ldcg((const float4*)(hh + src));
                *(float4*)(rsm + S_ALO + sw) = __ldcg((const float4*)(hl + src));
            }
        }
        __syncthreads();

        // ---- mma: full K=512, 8 independent acc chains ----
        float acc8[8][4];
#pragma unroll
        for (int p = 0; p < 8; p++)
#pragma unroll
            for (int e = 0; e < 4; e++) acc8[p][e] = 0.0f;

#pragma unroll
        for (int k16 = 0; k16 < 32; k16++) {
            const int kc = k16 >> 2;
            const uint32_t kb = (uint32_t)(k16 & 3) * 32;
            uint32_t ah[4], al[4], bh[2], bl[2];
            {
                uint32_t arow = (uint32_t)(kc * 16 + la);
                uint32_t sw = SWZ128(arow * 128 + kb + a_koff);
                ldsm_x4(ah, sb + S_AHI + sw);
                ldsm_x4(al, sb + S_ALO + sw);
            }
            {
                uint32_t brow = (uint32_t)(kc * 64 + wn * 8 + (la & 7));
                uint32_t sw = SWZ128(brow * 128 + kb + b_koff);
                ldsm_x2(bh, sb + S_BHI + sw);
                ldsm_x2(bl, sb + S_BLO + sw);
            }
            float* a0 = acc8[k16 & 7];
            mma_bf16(a0, ah, bh);
            mma_bf16(a0, ah, bl);
            mma_bf16(a0, al, bh);
        }
        float z0a = 0.f, z1a = 0.f, z2a = 0.f, z3a = 0.f;
#pragma unroll
        for (int p = 0; p < 8; p++) {
            z0a += acc8[p][0]; z1a += acc8[p][1]; z2a += acc8[p][2]; z3a += acc8[p][3];
        }

        // ---- exchange z through smem: z_s[col_local][b] ----
        {
            int c0 = wn * 8 + 2 * tig;
            z_s[c0 * 16 + g]             = z0a;
            z_s[(c0 + 1) * 16 + g]       = z1a;
            z_s[c0 * 16 + g + 8]         = z2a;
            z_s[(c0 + 1) * 16 + g + 8]   = z3a;
        }
        __syncthreads();

        // ---- gates: thread (u_l, b_l) reads its 4 gate columns ----
        {
            float z0 = z_s[(u_l * 4 + 0) * 16 + b_l] + zx0 + __ldg(bias + u);
            float z1 = z_s[(u_l * 4 + 1) * 16 + b_l] + zx1 + __ldg(bias + 512 + u);
            float z2 = z_s[(u_l * 4 + 2) * 16 + b_l] + zx2 + __ldg(bias + 1024 + u);
            float z3 = z_s[(u_l * 4 + 3) * 16 + b_l] + zx3 + __ldg(bias + 1536 + u);
            float ig = fsigmoid(z0);
            float fg = fsigmoid(z1);
            float gg = ftanh(z2);
            float og = fsigmoid(z3);
            float cv = fg * c_reg + ig * gg;
            c_reg = cv;
            float hv = og * ftanh(cv);
            __nv_bfloat16 hh = __float2bfloat16(hv);
            size_t slotoff = (size_t)((t & 3) * 4 + bg) * (16 * UU);
            g_hhi4[slotoff + hoff] = hh;
            g_hlo4[slotoff + hoff] = __float2bfloat16(hv - __bfloat162float(hh));
            if (t == TT - 1) out[(size_t)b_glob * UU + u] = hv;
        }
        bump_cnt(ctr);   // syncthreads inside also protects z_s/A reuse next step
    }
}

// =======================================================================
extern "C" void kernel_launch(void* const* d_in, const int* in_sizes, int n_in,
                              void* d_out, int out_size) {
    const float* x  = (const float*)d_in[0];
    const float* Wk = (const float*)d_in[1];
    const float* Wr = (const float*)d_in[2];
    const float* b  = (const float*)d_in[3];
    float* out = (float*)d_out;

    cudaFuncSetAttribute(gemm_zx_mma, cudaFuncAttributeMaxDynamicSharedMemorySize, GEMM_SMEM);
    cudaFuncSetAttribute(lstm_recur2, cudaFuncAttributeMaxDynamicSharedMemorySize, REC2_SMEM);

    // Resolve DEVICE addresses of __device__ symbols on the host.
    void *cnt_ptr, *wthi, *wtlo, *wrhi, *wrlo;
    cudaGetSymbolAddress(&cnt_ptr, g_cnt);
    cudaGetSymbolAddress(&wthi, g_wthi);
    cudaGetSymbolAddress(&wtlo, g_wtlo);
    cudaGetSymbolAddress(&wrhi, g_wrhi);
    cudaGetSymbolAddress(&wrlo, g_wrlo);

    cudaMemsetAsync(cnt_ptr, 0, 512 * sizeof(unsigned));   // graph-capturable

    prep_x<<<(MM * DD / 4 + 255) / 256, 256>>>(x);
    prep_wt<<<dim3(NG / 32, DD / 32), 256>>>(Wk, (__nv_bfloat16*)wthi, (__nv_bfloat16*)wtlo);
    prep_wr<<<dim3(NG / 32, DD / 32), 256>>>(Wr, (__nv_bfloat16*)wrhi, (__nv_bfloat16*)wrlo);
    gemm_zx_mma<<<dim3(NG / 128, MM / 128), 256, GEMM_SMEM>>>();
    lstm_recur2<<<128, 256, REC2_SMEM>>>(b, out);
}

// round 10
// speedup vs baseline: 1.4256x; 1.1777x over previous
#include <cuda_runtime.h>
#include <cuda_bf16.h>
#include <cstdint>

#define BB 64
#define TT 512
#define DD 512
#define UU 512
#define NG 2048       // 4*UU
#define MM (BB * TT)  // 32768

// ---------------- device scratch (static: no allocations allowed) ----------------
__device__ float g_zx[(size_t)MM * NG];              // 268 MB: x @ Wk
__device__ __nv_bfloat16 g_xhi[(size_t)MM * DD];     // 32 MB
__device__ __nv_bfloat16 g_xlo[(size_t)MM * DD];     // 32 MB
__device__ __nv_bfloat16 g_wthi[(size_t)NG * DD];    // 2 MB (Wk^T [N][K])
__device__ __nv_bfloat16 g_wtlo[(size_t)NG * DD];    // 2 MB
__device__ __nv_bfloat16 g_wrhi[(size_t)NG * DD];    // 2 MB (Wr^T, GATE-INTERLEAVED rows)
__device__ __nv_bfloat16 g_wrlo[(size_t)NG * DD];    // 2 MB
// hidden state 4-slot ring: [slot][bg][b_l*512 + u]  (16 batches per bg)
__device__ __nv_bfloat16 g_hhi4[4 * 4 * 16 * UU];
__device__ __nv_bfloat16 g_hlo4[4 * 4 * 16 * UU];
__device__ unsigned g_cnt[512];                      // counter per bg at [bg*32]

// ---------------- helpers (arch-agnostic PTX only: compiles via compute_103) -----
__device__ __forceinline__ uint32_t smem_u32(const void* p) {
    uint32_t a;
    asm("{ .reg .u64 t; cvta.to.shared.u64 t, %1; cvt.u32.u64 %0, t; }" : "=r"(a) : "l"(p));
    return a;
}
#define SWZ128(b) ((b) ^ (((b) >> 3) & 0x70))

__device__ __forceinline__ void cp16(uint32_t saddr, const void* gptr) {
    asm volatile("cp.async.cg.shared.global [%0], [%1], 16;" :: "r"(saddr), "l"(gptr) : "memory");
}
#define CP_COMMIT() asm volatile("cp.async.commit_group;" ::: "memory")
#define CP_WAIT1()  asm volatile("cp.async.wait_group 1;" ::: "memory")

__device__ __forceinline__ void ldsm_x4(uint32_t* r, uint32_t addr) {
    asm volatile("ldmatrix.sync.aligned.m8n8.x4.shared.b16 {%0,%1,%2,%3}, [%4];"
                 : "=r"(r[0]), "=r"(r[1]), "=r"(r[2]), "=r"(r[3]) : "r"(addr));
}
__device__ __forceinline__ void ldsm_x2(uint32_t* r, uint32_t addr) {
    asm volatile("ldmatrix.sync.aligned.m8n8.x2.shared.b16 {%0,%1}, [%2];"
                 : "=r"(r[0]), "=r"(r[1]) : "r"(addr));
}
__device__ __forceinline__ void mma_bf16(float* c, const uint32_t* a, const uint32_t* b) {
    asm volatile(
        "mma.sync.aligned.m16n8k16.row.col.f32.bf16.bf16.f32 "
        "{%0,%1,%2,%3}, {%4,%5,%6,%7}, {%8,%9}, {%0,%1,%2,%3};"
        : "+f"(c[0]), "+f"(c[1]), "+f"(c[2]), "+f"(c[3])
        : "r"(a[0]), "r"(a[1]), "r"(a[2]), "r"(a[3]), "r"(b[0]), "r"(b[1]));
}

// ---------------- sync: release RED bump / acquire poll ---------------------------
__device__ __forceinline__ void bump_cnt(unsigned* c) {
    __syncthreads();
    if (threadIdx.x == 0)
        asm volatile("red.release.gpu.global.add.u32 [%0], %1;" :: "l"(c), "r"(1u) : "memory");
}
// all-lane acquire poll (no CTA sync needed; each thread's loads ordered after it)
__device__ __forceinline__ void wait_cnt_all(unsigned* c, unsigned tgt) {
    unsigned v;
    do {
        asm volatile("ld.acquire.gpu.global.u32 %0, [%1];" : "=r"(v) : "l"(c) : "memory");
        if (v < tgt) __nanosleep(16);
    } while (v < tgt);
}

// ---------------- fast transcendentals ----------------
__device__ __forceinline__ float fsigmoid(float x) { return 1.0f / (1.0f + __expf(-x)); }
__device__ __forceinline__ float ftanh(float x) { return 2.0f / (1.0f + __expf(-2.0f * x)) - 1.0f; }

// =======================================================================
// Prep 1: x fp32 -> bf16 hi/lo split.
// =======================================================================
__global__ __launch_bounds__(256) void prep_x(const float* __restrict__ x) {
    size_t i = (size_t)blockIdx.x * 256 + threadIdx.x;
    const size_t n4 = (size_t)MM * DD / 4;
    if (i >= n4) return;
    float4 v = ((const float4*)x)[i];
    __nv_bfloat16 h0 = __float2bfloat16(v.x), h1 = __float2bfloat16(v.y);
    __nv_bfloat16 h2 = __float2bfloat16(v.z), h3 = __float2bfloat16(v.w);
    __nv_bfloat16 l0 = __float2bfloat16(v.x - __bfloat162float(h0));
    __nv_bfloat16 l1 = __float2bfloat16(v.y - __bfloat162float(h1));
    __nv_bfloat16 l2 = __float2bfloat16(v.z - __bfloat162float(h2));
    __nv_bfloat16 l3 = __float2bfloat16(v.w - __bfloat162float(h3));
    ((__nv_bfloat162*)g_xhi)[2 * i]     = __nv_bfloat162(h0, h1);
    ((__nv_bfloat162*)g_xhi)[2 * i + 1] = __nv_bfloat162(h2, h3);
    ((__nv_bfloat162*)g_xlo)[2 * i]     = __nv_bfloat162(l0, l1);
    ((__nv_bfloat162*)g_xlo)[2 * i + 1] = __nv_bfloat162(l2, l3);
}

// =======================================================================
// Prep 2a: Wk -> transposed bf16 hi/lo [N][K] (original column order).
// =======================================================================
__global__ __launch_bounds__(256) void prep_wt(const float* __restrict__ W,
                                               __nv_bfloat16* __restrict__ dhi,
                                               __nv_bfloat16* __restrict__ dlo) {
    __shared__ float s[32][33];
    const int n0 = blockIdx.x * 32;
    const int k0 = blockIdx.y * 32;
    const int tx = threadIdx.x & 31;
    const int ty = threadIdx.x >> 5;
#pragma unroll
    for (int j = 0; j < 32; j += 8)
        s[ty + j][tx] = W[(size_t)(k0 + ty + j) * NG + n0 + tx];
    __syncthreads();
#pragma unroll
    for (int j = 0; j < 32; j += 8) {
        float v = s[tx][ty + j];
        __nv_bfloat16 h = __float2bfloat16(v);
        __nv_bfloat16 l = __float2bfloat16(v - __bfloat162float(h));
        size_t o = (size_t)(n0 + ty + j) * DD + k0 + tx;
        dhi[o] = h;
        dlo[o] = l;
    }
}

// =======================================================================
// Prep 2b: Wr -> transposed bf16 hi/lo, GATE-INTERLEAVED rows:
// output row n' = (n % 512)*4 + (n / 512)  (unit-major, gate-minor).
// =======================================================================
__global__ __launch_bounds__(256) void prep_wr(const float* __restrict__ W,
                                               __nv_bfloat16* __restrict__ dhi,
                                               __nv_bfloat16* __restrict__ dlo) {
    __shared__ float s[32][33];
    const int n0 = blockIdx.x * 32;
    const int k0 = blockIdx.y * 32;
    const int tx = threadIdx.x & 31;
    const int ty = threadIdx.x >> 5;
#pragma unroll
    for (int j = 0; j < 32; j += 8)
        s[ty + j][tx] = W[(size_t)(k0 + ty + j) * NG + n0 + tx];
    __syncthreads();
#pragma unroll
    for (int j = 0; j < 32; j += 8) {
        float v = s[tx][ty + j];
        __nv_bfloat16 h = __float2bfloat16(v);
        __nv_bfloat16 l = __float2bfloat16(v - __bfloat162float(h));
        int n = n0 + ty + j;
        int nperm = (n & 511) * 4 + (n >> 9);
        size_t o = (size_t)nperm * DD + k0 + tx;
        dhi[o] = h;
        dlo[o] = l;
    }
}

// =======================================================================
// Phase 1 GEMM (mma.sync bf16 x3): zx = x @ Wk   (validated R3/R5/R7)
// =======================================================================
#define STAGE_BYTES 65536
#define SA_HI 0
#define SA_LO 16384
#define SB_HI 32768
#define SB_LO 49152
#define GEMM_SMEM (2 * STAGE_BYTES)

__device__ __forceinline__ void load_stage(uint32_t sbase, int m0, int n0, int kc, int tid) {
    const uint32_t ksrc = (uint32_t)kc * 128;
    const char* pxh = (const char*)g_xhi;
    const char* pxl = (const char*)g_xlo;
    const char* pwh = (const char*)g_wthi;
    const char* pwl = (const char*)g_wtlo;
#pragma unroll
    for (int i = 0; i < 4; i++) {
        int idx = i * 256 + tid;
        int row = idx >> 3;
        uint32_t q = (uint32_t)(idx & 7) * 16;
        uint32_t sw = SWZ128((uint32_t)row * 128 + q);
        size_t asrc = (size_t)(m0 + row) * 1024 + ksrc + q;
        size_t bsrc = (size_t)(n0 + row) * 1024 + ksrc + q;
        cp16(sbase + SA_HI + sw, pxh + asrc);
        cp16(sbase + SA_LO + sw, pxl + asrc);
        cp16(sbase + SB_HI + sw, pwh + bsrc);
        cp16(sbase + SB_LO + sw, pwl + bsrc);
    }
}

__global__ __launch_bounds__(256) void gemm_zx_mma() {
    extern __shared__ __align__(1024) char smem[];
    const uint32_t sb = smem_u32(smem);
    const int tid = threadIdx.x;
    const int wid = tid >> 5, lid = tid & 31;
    const int n0 = blockIdx.x * 128, m0 = blockIdx.y * 128;
    const int wm = wid & 1;
    const int wn = wid >> 1;

    float acc[4][4][4];
#pragma unroll
    for (int mf = 0; mf < 4; mf++)
#pragma unroll
        for (int nf = 0; nf < 4; nf++)
#pragma unroll
            for (int e = 0; e < 4; e++) acc[mf][nf][e] = 0.0f;

    load_stage(sb, m0, n0, 0, tid);
    CP_COMMIT();

    for (int kc = 0; kc < 8; kc++) {
        if (kc < 7) load_stage(sb + ((kc + 1) & 1) * STAGE_BYTES, m0, n0, kc + 1, tid);
        CP_COMMIT();
        CP_WAIT1();
        __syncthreads();

        const uint32_t st = sb + (kc & 1) * STAGE_BYTES;
        const int la = lid & 15;
        const uint32_t a_koff = (uint32_t)(lid >> 4) * 16;
        const uint32_t b_koff = (uint32_t)((la >> 3) & 1) * 16;

#pragma unroll
        for (int k16 = 0; k16 < 4; k16++) {
            const uint32_t kb = (uint32_t)k16 * 32;
            uint32_t ah[4][4], al[4][4];
#pragma unroll
            for (int mf = 0; mf < 4; mf++) {
                uint32_t row = (uint32_t)(wm * 64 + mf * 16 + la);
                uint32_t sw = SWZ128(row * 128 + kb + a_koff);
                ldsm_x4(ah[mf], st + SA_HI + sw);
                ldsm_x4(al[mf], st + SA_LO + sw);
            }
            uint32_t bh[4][2], bl[4][2];
#pragma unroll
            for (int nf = 0; nf < 4; nf++) {
                uint32_t nrow = (uint32_t)(wn * 32 + nf * 8 + (la & 7));
                uint32_t sw = SWZ128(nrow * 128 + kb + b_koff);
                ldsm_x2(bh[nf], st + SB_HI + sw);
                ldsm_x2(bl[nf], st + SB_LO + sw);
            }
#pragma unroll
            for (int mf = 0; mf < 4; mf++)
#pragma unroll
                for (int nf = 0; nf < 4; nf++) {
                    mma_bf16(acc[mf][nf], ah[mf], bh[nf]);
                    mma_bf16(acc[mf][nf], ah[mf], bl[nf]);
                    mma_bf16(acc[mf][nf], al[mf], bh[nf]);
                }
        }
        __syncthreads();
    }

    const int g = lid >> 2, tig = lid & 3;
#pragma unroll
    for (int mf = 0; mf < 4; mf++) {
        int row = m0 + wm * 64 + mf * 16 + g;
        float* b0 = g_zx + (size_t)row * NG + n0 + wn * 32;
        float* b1 = b0 + (size_t)8 * NG;
#pragma unroll
        for (int nf = 0; nf < 4; nf++) {
            *(float2*)(b0 + nf * 8 + 2 * tig) = make_float2(acc[mf][nf][0], acc[mf][nf][1]);
            *(float2*)(b1 + nf * 8 + 2 * tig) = make_float2(acc[mf][nf][2], acc[mf][nf][3]);
        }
    }
}

// =======================================================================
// Phase 2: persistent LSTM recurrence — role-swapped MMA + split-K warps.
// 128 CTAs = 32 col-groups (16 units = 64 gate-cols) x 4 batch-groups
// (16 batches). Warp w owns K-chunk kc=w (64 K): A = Wr' (m=cols),
// B = h (n=batches). Every smem byte read ONCE per step. Per-warp
// wait+stage+mma (no CTA sync); one syncthreads before the zred reduce.
// =======================================================================
#define S_WHI 0                         // Wr hi: 512 rows (kc*64+c) x 128B
#define S_WLO 65536
#define S_HHI 131072                    // h hi: 128 rows (kc*16+b) x 128B
#define S_HLO 147456
#define S_Z   163840                    // zred: [w(8)][c(64)][b pad 20] fp32
#define ZPAD 20
#define REC3_SMEM (S_Z + 8 * 64 * ZPAD * 4)   // 204800

__global__ __launch_bounds__(256) void lstm_recur3(const float* __restrict__ bias,
                                                   float* __restrict__ out) {
    extern __shared__ __align__(1024) char rsm[];
    const uint32_t sb = smem_u32(rsm);
    const int tid = threadIdx.x;
    const int wid = tid >> 5, lid = tid & 31;
    const int blk = blockIdx.x;
    const int bg = blk & 3;     // batch group: batches [bg*16, +16)
    const int cg = blk >> 2;    // col group: units [cg*16, +16) = cols' [cg*64, +64)
    unsigned* ctr = &g_cnt[bg * 32];

    // ---- fill persistent Wr' slice: rows kc*64+c (512) x 128B, hi/lo ----
    {
        const char* wh = (const char*)g_wrhi;
        const char* wl = (const char*)g_wrlo;
#pragma unroll
        for (int r = 0; r < 16; r++) {
            int i = r * 256 + tid;            // 0..4095
            int rowf = i >> 3;                // 0..511 = kc*64 + c
            uint32_t q = (uint32_t)(i & 7) * 16;
            int kc = rowf >> 6, c = rowf & 63;
            uint32_t sw = SWZ128((uint32_t)rowf * 128 + q);
            size_t src = (size_t)(cg * 64 + c) * 1024 + (size_t)kc * 128 + q;
            *(float4*)(rsm + S_WHI + sw) = *(const float4*)(wh + src);
            *(float4*)(rsm + S_WLO + sw) = *(const float4*)(wl + src);
        }
    }

    // ---- gate ownership: tid = u_l*16 + b_l ----
    const int u_l = tid >> 4;           // 0..15
    const int b_l = tid & 15;           // 0..15
    const int u = cg * 16 + u_l;        // unit 0..511
    const int b_glob = bg * 16 + b_l;   // batch 0..63
    const int hoff = b_l * UU + u;      // within [slot][bg] block

    // h(-1) = 0 into slot 3; bump announces (syncthreads inside orders Wr fill too)
    g_hhi4[(3 * 4 + bg) * (16 * UU) + hoff] = __float2bfloat16(0.0f);
    g_hlo4[(3 * 4 + bg) * (16 * UU) + hoff] = __float2bfloat16(0.0f);
    float c_reg = 0.0f;
    bump_cnt(ctr);                      // counter reaches 32 == h(-1) ready

    const int la = lid & 15;
    const uint32_t a_koff = (uint32_t)(lid >> 4) * 16;
    const uint32_t b_koff = (uint32_t)((la >> 3) & 1) * 16;
    const int g = lid >> 2, tig = lid & 3;
    float* zred = (float*)(rsm + S_Z);

    for (int t = 0; t < TT; t++) {
        // ---- prefetch zx(t) (independent of all sync) ----
        const float* zxp = &g_zx[((size_t)b_glob * TT + t) * NG + u];
        float zx0 = __ldg(zxp);
        float zx1 = __ldg(zxp + 512);
        float zx2 = __ldg(zxp + 1024);
        float zx3 = __ldg(zxp + 1536);

        // ---- per-thread acquire wait for group h(t-1) ----
        wait_cnt_all(ctr, 32u * (unsigned)(t + 1));

        // ---- per-warp stage: own h rows kc=wid (16 b x 128B, hi/lo) ----
        {
            const char* hh = (const char*)g_hhi4 + (size_t)(((t + 3) & 3) * 4 + bg) * (16 * UU) * 2;
            const char* hl = (const char*)g_hlo4 + (size_t)(((t + 3) & 3) * 4 + bg) * (16 * UU) * 2;
#pragma unroll
            for (int r = 0; r < 4; r++) {
                int i = r * 32 + lid;           // 0..127
                int b = i >> 3;                 // 0..15
                uint32_t q = (uint32_t)(i & 7) * 16;
                uint32_t rowf = (uint32_t)(wid * 16 + b);
                uint32_t sw = SWZ128(rowf * 128 + q);
                size_t src = (size_t)b * 1024 + (size_t)wid * 128 + q;
                *(float4*)(rsm + S_HHI + sw) = __ldcg((const float4*)(hh + src));
                *(float4*)(rsm + S_HLO + sw) = __ldcg((const float4*)(hl + src));
            }
        }
        __syncwarp();

        // ---- mma: warp's K-chunk (4 k16), A=Wr (4 mf), B=h (2 nf) ----
        float acc[4][2][4];
#pragma unroll
        for (int mf = 0; mf < 4; mf++)
#pragma unroll
            for (int nf = 0; nf < 2; nf++)
#pragma unroll
                for (int e = 0; e < 4; e++) acc[mf][nf][e] = 0.0f;

#pragma unroll
        for (int k16 = 0; k16 < 4; k16++) {
            const uint32_t kb = (uint32_t)k16 * 32;
            uint32_t bh[2][2], blo[2][2];
#pragma unroll
            for (int nf = 0; nf < 2; nf++) {
                uint32_t brow = (uint32_t)(wid * 16 + nf * 8 + (la & 7));
                uint32_t sw = SWZ128(brow * 128 + kb + b_koff);
                ldsm_x2(bh[nf], sb + S_HHI + sw);
                ldsm_x2(blo[nf], sb + S_HLO + sw);
            }
#pragma unroll
            for (int mf = 0; mf < 4; mf++) {
                uint32_t arow = (uint32_t)(wid * 64 + mf * 16 + la);
                uint32_t sw = SWZ128(arow * 128 + kb + a_koff);
                uint32_t ah[4], alo[4];
                ldsm_x4(ah, sb + S_WHI + sw);
                ldsm_x4(alo, sb + S_WLO + sw);
#pragma unroll
                for (int nf = 0; nf < 2; nf++) {
                    mma_bf16(acc[mf][nf], ah, bh[nf]);
                    mma_bf16(acc[mf][nf], ah, blo[nf]);
                    mma_bf16(acc[mf][nf], alo, bh[nf]);
                }
            }
        }

        // ---- write warp partials to zred [wid][c][b pad 20] ----
#pragma unroll
        for (int mf = 0; mf < 4; mf++) {
#pragma unroll
            for (int nf = 0; nf < 2; nf++) {
                int c0 = mf * 16 + g;
                int b0 = nf * 8 + 2 * tig;
                float* zp = zred + ((size_t)wid * 64 + c0) * ZPAD + b0;
                *(float2*)zp = make_float2(acc[mf][nf][0], acc[mf][nf][1]);
                *(float2*)(zp + 8 * ZPAD) = make_float2(acc[mf][nf][2], acc[mf][nf][3]);
            }
        }
        __syncthreads();

        // ---- reduce 8 partials + gates (thread (u_l, b_l)) ----
        {
            float z0 = zx0 + __ldg(bias + u);
            float z1 = zx1 + __ldg(bias + 512 + u);
            float z2 = zx2 + __ldg(bias + 1024 + u);
            float z3 = zx3 + __ldg(bias + 1536 + u);
#pragma unroll
            for (int w = 0; w < 8; w++) {
                const float* zp = zred + ((size_t)w * 64 + u_l * 4) * ZPAD + b_l;
                z0 += zp[0];
                z1 += zp[ZPAD];
                z2 += zp[2 * ZPAD];
                z3 += zp[3 * ZPAD];
            }
            float ig = fsigmoid(z0);
            float fg = fsigmoid(z1);
            float gg = ftanh(z2);
            float og = fsigmoid(z3);
            float cv = fg * c_reg + ig * gg;
            c_reg = cv;
            float hv = og * ftanh(cv);
            __nv_bfloat16 hh = __float2bfloat16(hv);
            size_t slotoff = (size_t)((t & 3) * 4 + bg) * (16 * UU);
            g_hhi4[slotoff + hoff] = hh;
            g_hlo4[slotoff + hoff] = __float2bfloat16(hv - __bfloat162float(hh));
            if (t == TT - 1) out[(size_t)b_glob * UU + u] = hv;
        }
        bump_cnt(ctr);   // syncthreads inside also protects zred reuse next step
    }
}

// =======================================================================
extern "C" void kernel_launch(void* const* d_in, const int* in_sizes, int n_in,
                              void* d_out, int out_size) {
    const float* x  = (const float*)d_in[0];
    const float* Wk = (const float*)d_in[1];
    const float* Wr = (const float*)d_in[2];
    const float* b  = (const float*)d_in[3];
    float* out = (float*)d_out;

    cudaFuncSetAttribute(gemm_zx_mma, cudaFuncAttributeMaxDynamicSharedMemorySize, GEMM_SMEM);
    cudaFuncSetAttribute(lstm_recur3, cudaFuncAttributeMaxDynamicSharedMemorySize, REC3_SMEM);

    // Resolve DEVICE addresses of __device__ symbols on the host.
    void *cnt_ptr, *wthi, *wtlo, *wrhi, *wrlo;
    cudaGetSymbolAddress(&cnt_ptr, g_cnt);
    cudaGetSymbolAddress(&wthi, g_wthi);
    cudaGetSymbolAddress(&wtlo, g_wtlo);
    cudaGetSymbolAddress(&wrhi, g_wrhi);
    cudaGetSymbolAddress(&wrlo, g_wrlo);

    cudaMemsetAsync(cnt_ptr, 0, 512 * sizeof(unsigned));   // graph-capturable

    prep_x<<<(MM * DD / 4 + 255) / 256, 256>>>(x);
    prep_wt<<<dim3(NG / 32, DD / 32), 256>>>(Wk, (__nv_bfloat16*)wthi, (__nv_bfloat16*)wtlo);
    prep_wr<<<dim3(NG / 32, DD / 32), 256>>>(Wr, (__nv_bfloat16*)wrhi, (__nv_bfloat16*)wrlo);
    gemm_zx_mma<<<dim3(NG / 128, MM / 128), 256, GEMM_SMEM>>>();
    lstm_recur3<<<128, 256, REC3_SMEM>>>(b, out);
}